// round 6
// baseline (speedup 1.0000x reference)
#include <cuda_runtime.h>
#include <stdint.h>

// PicMix: output = two index-function masks, no input read.
// Flattened: [mask_a (8,12,512,512) fp32][mask_b same]. 192 planes of 512x512.
// group g = (ch%12)/3; isB = second mask.
//   g0: a=1,b=0 | g1: a=(i%2==j%2) | g2: a=i%2 | g3: a=j%2 ; b = complement.
//
// R6: TMA bulk-store experiment. Every plane's content is a 2-row (4KB)
// repeating pattern. Each CTA: build the 4KB pattern in SMEM (1 float4 per
// thread), fence to the async proxy, then ONE elected thread issues 16x
// cp.async.bulk shared->global (4KB each) covering the CTA's 64KB segment.
// This writes full 128B lines via the async proxy, bypassing the SM STG
// sector-write path that R1-R5 plateaued on (~7.2 TB/s, no counter >71%).

static constexpr int PLANE_F4         = 65536;  // 512*512/4
static constexpr int BLOCKS_PER_PLANE = 16;
static constexpr int F4_PER_BLOCK     = PLANE_F4 / BLOCKS_PER_PLANE; // 4096 f4 = 64KB
static constexpr int THREADS          = 256;
static constexpr int COPY_BYTES       = 4096;   // 2 rows = 256 f4
static constexpr int COPIES_PER_BLOCK = F4_PER_BLOCK * 16 / COPY_BYTES; // 16

__device__ __forceinline__ uint32_t smem_u32(const void* p) {
    uint32_t a;
    asm("{ .reg .u64 t; cvta.to.shared.u64 t, %1; cvt.u32.u64 %0, t; }"
        : "=r"(a) : "l"(p));
    return a;
}

__global__ void __launch_bounds__(THREADS) picmix_kernel(float4* __restrict__ out) {
    __shared__ __align__(128) float4 pat[THREADS];   // 4KB = one 2-row pattern

    int plane = blockIdx.x >> 4;        // BLOCKS_PER_PLANE = 16
    int seg   = blockIdx.x & 15;
    int t     = threadIdx.x;

    // Pattern slot t covers f4 index t of a 2-row block: row parity = t>>7.
    int ip  = (t >> 7) & 1;

    int isB = plane >= 96;              // 96 planes per mask
    int pin = plane - (isB ? 96 : 0);
    int ch  = pin % 12;
    int g   = ch * 0x5556 >> 16;        // ch/3 for ch in [0,12)

    float e, o;                         // even-j value, odd-j value (mask_a)
    if (g == 0) {
        e = o = 1.0f;
    } else if (g == 1) {
        e = (ip == 0) ? 1.0f : 0.0f;
        o = 1.0f - e;
    } else if (g == 2) {
        e = o = (float)ip;
    } else {
        e = 0.0f; o = 1.0f;
    }
    if (isB) {                          // mask_b: 0 for g0, complement otherwise
        if (g == 0) { e = 0.0f; o = 0.0f; }
        else        { e = 1.0f - e; o = 1.0f - o; }
    }

    pat[t] = make_float4(e, o, e, o);
    __syncthreads();

    if (t == 0) {
        // Publish generic-proxy SMEM writes to the async proxy.
        asm volatile("fence.proxy.async.shared::cta;" ::: "memory");

        uint32_t src = smem_u32(pat);
        float4* dst = out + plane * PLANE_F4 + seg * F4_PER_BLOCK;
        #pragma unroll
        for (int k = 0; k < COPIES_PER_BLOCK; k++) {
            asm volatile(
                "cp.async.bulk.global.shared::cta.bulk_group [%0], [%1], %2;"
                :: "l"(dst + k * (COPY_BYTES / 16)), "r"(src), "n"(COPY_BYTES)
                : "memory");
        }
        asm volatile("cp.async.bulk.commit_group;" ::: "memory");
        asm volatile("cp.async.bulk.wait_group 0;" ::: "memory");
    }
}

extern "C" void kernel_launch(void* const* d_in, const int* in_sizes, int n_in,
                              void* d_out, int out_size) {
    (void)d_in; (void)in_sizes; (void)n_in; (void)out_size;
    // out_size = 50,331,648 fp32 = 192 planes * 65536 f4
    int blocks = 192 * BLOCKS_PER_PLANE;  // 3072
    picmix_kernel<<<blocks, THREADS>>>((float4*)d_out);
}

// round 7
// speedup vs baseline: 1.1513x; 1.1513x over previous
#include <cuda_runtime.h>
#include <stdint.h>

// PicMix: output = two index-function masks, no input read.
// Flattened: [mask_a (8,12,512,512) fp32][mask_b same]. 192 planes of 512x512.
// group g = (ch%12)/3; isB = second mask.
//   g0: a=1,b=0 | g1: a=(i%2==j%2) | g2: a=i%2 | g3: a=j%2 ; b = complement.
// Each float4 covers j..j+3 (even start) -> lanes are (even,odd,even,odd).
//
// FINAL (R7 = R4 sweep optimum): 12288 CTAs x 256 thr x 4 float4/thread.
// Thread stride = 256 f4 = exactly 2 rows, so row parity (and the store
// value) is constant per thread: decode once, 4x STG.E.128 at immediate
// offsets. Session evidence: STG (4 shapes), STG.CS, and TMA bulk-store all
// plateau at 28.0-30.7us ncu / 58-64% DRAM -> chip LTS write cap
// (~6300 B/cyc, path-independent). 201.3 MB of mandatory output / ~7.2 TB/s
// L2-side store throughput = ~28us floor; this config measured best (28.03us).

static constexpr int PLANE_F4         = 65536;  // 512*512/4
static constexpr int BLOCKS_PER_PLANE = 64;
static constexpr int F4_PER_BLOCK     = PLANE_F4 / BLOCKS_PER_PLANE; // 1024
static constexpr int THREADS          = 256;
static constexpr int F4_PER_THREAD    = F4_PER_BLOCK / THREADS;      // 4

__global__ void __launch_bounds__(THREADS) picmix_kernel(float4* __restrict__ out) {
    int plane = blockIdx.x >> 6;        // BLOCKS_PER_PLANE = 64
    int seg   = blockIdx.x & 63;

    int base = plane * PLANE_F4 + seg * F4_PER_BLOCK + threadIdx.x;
    int ip   = (base >> 7) & 1;         // row parity; invariant across strided stores

    int isB = plane >= 96;              // 96 planes per mask
    int pin = isB ? plane - 96 : plane;
    int ch  = pin % 12;
    int g   = ch * 0x5556 >> 16;        // ch/3 for ch in [0,12)

    float e, o;                         // even-j value, odd-j value
    if (g == 0) {
        e = o = isB ? 0.0f : 1.0f;
    } else if (g == 1) {
        float s = (ip == 0) ? 1.0f : 0.0f;   // mask_a even lane
        e = isB ? 1.0f - s : s;
        o = 1.0f - e;
    } else if (g == 2) {
        float v = (float)ip;
        e = o = isB ? 1.0f - v : v;
    } else {
        e = isB ? 1.0f : 0.0f;
        o = 1.0f - e;
    }

    float4 v4 = make_float4(e, o, e, o);
    float4* p = out + base;
    #pragma unroll
    for (int k = 0; k < F4_PER_THREAD; k++) {
        p[k * THREADS] = v4;            // stride 256 f4 = 4KB = 2 rows
    }
}

extern "C" void kernel_launch(void* const* d_in, const int* in_sizes, int n_in,
                              void* d_out, int out_size) {
    (void)d_in; (void)in_sizes; (void)n_in; (void)out_size;
    // out_size = 50,331,648 fp32 = 192 planes * 65536 f4
    int blocks = 192 * BLOCKS_PER_PLANE;  // 12288
    picmix_kernel<<<blocks, THREADS>>>((float4*)d_out);
}